// round 1
// baseline (speedup 1.0000x reference)
#include <cuda_runtime.h>
#include <math.h>

// Sinkhorn distance: B=16, Lx=Ly=1024, D=256, eps=0.1, 50 iters.
// All log-domain quantities are kept in log2 units:
//   lk2 = -cost * (10/ln2),  log_mu2 = log_nu2 = -log2(1024) = -10
// LSE2(x) = log2 sum 2^x  — identical recursion to the reference divided by ln2.

#define BATCH 16
#define LSEQ  1024
#define DDIM  256
#define K2C   14.426950408889634f   // 10 / ln(2)

__device__ float g_cost[(size_t)BATCH * LSEQ * LSEQ];  // 64 MB scratch
__device__ float g_x2[BATCH * LSEQ];
__device__ float g_y2[BATCH * LSEQ];
__device__ float g_lu[BATCH * LSEQ];
__device__ float g_lv[BATCH * LSEQ];
__device__ float g_part[2048];

static __device__ __forceinline__ float ex2f(float x) {
    float r; asm("ex2.approx.ftz.f32 %0, %1;" : "=f"(r) : "f"(x)); return r;
}
static __device__ __forceinline__ float lg2f(float x) {
    float r; asm("lg2.approx.ftz.f32 %0, %1;" : "=f"(r) : "f"(x)); return r;
}

typedef unsigned long long ull;
static __device__ __forceinline__ ull pack2(float lo, float hi) {
    ull r; asm("mov.b64 %0, {%1, %2};" : "=l"(r) : "f"(lo), "f"(hi)); return r;
}
static __device__ __forceinline__ float2 unpack2(ull v) {
    float2 r; asm("mov.b64 {%0, %1}, %2;" : "=f"(r.x), "=f"(r.y) : "l"(v)); return r;
}
static __device__ __forceinline__ void ffma2(ull& d, ull a, ull b) {
    asm("fma.rn.f32x2 %0, %1, %2, %0;" : "+l"(d) : "l"(a), "l"(b));
}

// ---------------------------------------------------------------------------
// Kernel 1: row sums of squares for x and y; also zero-init log_u / log_v.
// One warp per row (32768 rows total). grid 4096 x 256 threads.
// ---------------------------------------------------------------------------
__global__ __launch_bounds__(256) void sumsq_kernel(const float* __restrict__ x,
                                                    const float* __restrict__ y) {
    int warp = (blockIdx.x * 256 + threadIdx.x) >> 5;
    int lane = threadIdx.x & 31;
    int isx = (warp < BATCH * LSEQ);
    int r = isx ? warp : warp - BATCH * LSEQ;
    const float* src = isx ? x : y;
    const float4* p = (const float4*)(src + (size_t)r * DDIM);
    float s = 0.f;
#pragma unroll
    for (int t = 0; t < 2; t++) {
        float4 v = p[lane + 32 * t];
        s += v.x * v.x + v.y * v.y + v.z * v.z + v.w * v.w;
    }
#pragma unroll
    for (int o = 16; o; o >>= 1) s += __shfl_xor_sync(0xffffffffu, s, o);
    if (lane == 0) {
        if (isx) { g_x2[r] = s; g_lu[r] = 0.f; }
        else     { g_y2[r] = s; g_lv[r] = 0.f; }
    }
}

// ---------------------------------------------------------------------------
// Kernel 2: batched cost GEMM.  cost = sqrt(max(x2 + y2 - 2*x@y^T, 0)).
// 128x128 tile, BK=8, 256 threads, 8x8 microtile, packed f32x2 FMAs.
// grid (8 coltiles, 8 rowtiles, 16 batches).
// ---------------------------------------------------------------------------
__global__ __launch_bounds__(256, 2) void cost_kernel(const float* __restrict__ x,
                                                      const float* __restrict__ y) {
    __shared__ __align__(16) float As[8][128];
    __shared__ __align__(16) float Bs[8][128];
    int b = blockIdx.z;
    int i0 = blockIdx.y * 128;
    int j0 = blockIdx.x * 128;
    int tid = threadIdx.x;
    int tx = tid & 15, ty = tid >> 4;
    const float* xb = x + (size_t)b * LSEQ * DDIM;
    const float* yb = y + (size_t)b * LSEQ * DDIM;
    int lr = tid >> 1;            // load row 0..127
    int lc = (tid & 1) * 4;       // load col group 0 or 4

    ull acc[8][4];
#pragma unroll
    for (int ri = 0; ri < 8; ri++)
#pragma unroll
        for (int cj = 0; cj < 4; cj++) acc[ri][cj] = 0ull;

    for (int k0 = 0; k0 < DDIM; k0 += 8) {
        float4 av = *(const float4*)(xb + (size_t)(i0 + lr) * DDIM + k0 + lc);
        float4 bv = *(const float4*)(yb + (size_t)(j0 + lr) * DDIM + k0 + lc);
        __syncthreads();
        As[lc + 0][lr] = av.x; As[lc + 1][lr] = av.y;
        As[lc + 2][lr] = av.z; As[lc + 3][lr] = av.w;
        Bs[lc + 0][lr] = bv.x; Bs[lc + 1][lr] = bv.y;
        Bs[lc + 2][lr] = bv.z; Bs[lc + 3][lr] = bv.w;
        __syncthreads();
#pragma unroll
        for (int kk = 0; kk < 8; kk++) {
            float4 a0 = *(const float4*)&As[kk][ty * 8];
            float4 a1 = *(const float4*)&As[kk][ty * 8 + 4];
            float4 b0 = *(const float4*)&Bs[kk][tx * 8];
            float4 b1 = *(const float4*)&Bs[kk][tx * 8 + 4];
            ull bp[4];
            bp[0] = pack2(b0.x, b0.y); bp[1] = pack2(b0.z, b0.w);
            bp[2] = pack2(b1.x, b1.y); bp[3] = pack2(b1.z, b1.w);
            float a[8] = {a0.x, a0.y, a0.z, a0.w, a1.x, a1.y, a1.z, a1.w};
#pragma unroll
            for (int ri = 0; ri < 8; ri++) {
                ull ap = pack2(a[ri], a[ri]);
#pragma unroll
                for (int cj = 0; cj < 4; cj++) ffma2(acc[ri][cj], ap, bp[cj]);
            }
        }
    }

    float x2r[8], y2c[8];
#pragma unroll
    for (int ri = 0; ri < 8; ri++) x2r[ri] = g_x2[b * LSEQ + i0 + ty * 8 + ri];
#pragma unroll
    for (int c = 0; c < 8; c++)    y2c[c]  = g_y2[b * LSEQ + j0 + tx * 8 + c];

#pragma unroll
    for (int ri = 0; ri < 8; ri++) {
        float out[8];
#pragma unroll
        for (int cj = 0; cj < 4; cj++) {
            float2 u = unpack2(acc[ri][cj]);
            out[2 * cj] = u.x; out[2 * cj + 1] = u.y;
        }
#pragma unroll
        for (int c = 0; c < 8; c++) {
            float d2 = x2r[ri] + y2c[c] - 2.f * out[c];
            out[c] = sqrtf(fmaxf(d2, 0.f));
        }
        float* dst = g_cost + ((size_t)b << 20) + (size_t)(i0 + ty * 8 + ri) * LSEQ + j0 + tx * 8;
        *(float4*)dst       = make_float4(out[0], out[1], out[2], out[3]);
        *(float4*)(dst + 4) = make_float4(out[4], out[5], out[6], out[7]);
    }
}

// ---------------------------------------------------------------------------
// Kernel 3: row LSE update.  log_u = -10 - LSE2_j(lv[j] - K2*c[i,j]).
// One warp per row; entire 1024-elem row held in registers (exact max, 1 exp/elem).
// grid 2048 x 256 (8 warps/block).
// ---------------------------------------------------------------------------
__global__ __launch_bounds__(256) void row_lse(void) {
    int row = blockIdx.x * 8 + (threadIdx.x >> 5);
    int lane = threadIdx.x & 31;
    int b = row >> 10;
    const float4* c4 = (const float4*)(g_cost + ((size_t)row << 10));
    const float4* v4 = (const float4*)(g_lv + (b << 10));
    float a[32];
#pragma unroll
    for (int t = 0; t < 8; t++) {
        float4 c = c4[lane + 32 * t];
        float4 v = v4[lane + 32 * t];
        a[4 * t + 0] = fmaf(c.x, -K2C, v.x);
        a[4 * t + 1] = fmaf(c.y, -K2C, v.y);
        a[4 * t + 2] = fmaf(c.z, -K2C, v.z);
        a[4 * t + 3] = fmaf(c.w, -K2C, v.w);
    }
    float m = a[0];
#pragma unroll
    for (int e = 1; e < 32; e++) m = fmaxf(m, a[e]);
#pragma unroll
    for (int o = 16; o; o >>= 1) m = fmaxf(m, __shfl_xor_sync(0xffffffffu, m, o));
    float s = 0.f;
#pragma unroll
    for (int e = 0; e < 32; e++) s += ex2f(a[e] - m);
#pragma unroll
    for (int o = 16; o; o >>= 1) s += __shfl_xor_sync(0xffffffffu, s, o);
    if (lane == 0) g_lu[row] = -10.f - (m + lg2f(s));
}

// ---------------------------------------------------------------------------
// Kernel 4: column LSE update.  log_v = -10 - LSE2_i(lu[i] - K2*c[i,j]).
// Thread-per-column (coalesced), 32-row register chunks with chunk-max merge.
// grid (8 coltiles, 16 batches) x 128 threads.
// ---------------------------------------------------------------------------
__global__ __launch_bounds__(128) void col_lse(void) {
    __shared__ float slu[1024];
    int b = blockIdx.y;
    int col = blockIdx.x * 128 + threadIdx.x;
#pragma unroll
    for (int k = threadIdx.x; k < 1024; k += 128) slu[k] = g_lu[(b << 10) + k];
    __syncthreads();
    const float* base = g_cost + ((size_t)b << 20) + col;
    float m = -1e30f, s = 0.f;
    for (int ch = 0; ch < 32; ch++) {
        float a[32];
#pragma unroll
        for (int r = 0; r < 32; r++) {
            float c = __ldg(base + ((size_t)(ch * 32 + r) << 10));
            a[r] = fmaf(c, -K2C, slu[ch * 32 + r]);
        }
        float cm = a[0];
#pragma unroll
        for (int r = 1; r < 32; r++) cm = fmaxf(cm, a[r]);
        float M = fmaxf(m, cm);
        s *= ex2f(m - M);
#pragma unroll
        for (int r = 0; r < 32; r++) s += ex2f(a[r] - M);
        m = M;
    }
    g_lv[(b << 10) + col] = -10.f - (m + lg2f(s));
}

// ---------------------------------------------------------------------------
// Kernel 5: transport sum.  sum_ij 2^(lu_i + lv_j - K2*c) * c  (per block partial).
// Warp per row; deterministic block partials (no atomics).
// ---------------------------------------------------------------------------
__global__ __launch_bounds__(256) void transport_kernel(void) {
    __shared__ float wsum[8];
    int w = threadIdx.x >> 5;
    int row = blockIdx.x * 8 + w;
    int lane = threadIdx.x & 31;
    int b = row >> 10;
    float luI = g_lu[row];
    const float4* c4 = (const float4*)(g_cost + ((size_t)row << 10));
    const float4* v4 = (const float4*)(g_lv + (b << 10));
    float s = 0.f;
#pragma unroll
    for (int t = 0; t < 8; t++) {
        float4 c = c4[lane + 32 * t];
        float4 v = v4[lane + 32 * t];
        s += ex2f(fmaf(c.x, -K2C, luI + v.x)) * c.x;
        s += ex2f(fmaf(c.y, -K2C, luI + v.y)) * c.y;
        s += ex2f(fmaf(c.z, -K2C, luI + v.z)) * c.z;
        s += ex2f(fmaf(c.w, -K2C, luI + v.w)) * c.w;
    }
#pragma unroll
    for (int o = 16; o; o >>= 1) s += __shfl_xor_sync(0xffffffffu, s, o);
    if (lane == 0) wsum[w] = s;
    __syncthreads();
    if (threadIdx.x == 0) {
        float t = 0.f;
#pragma unroll
        for (int i = 0; i < 8; i++) t += wsum[i];
        g_part[blockIdx.x] = t;
    }
}

__global__ __launch_bounds__(256) void finalize_kernel(float* __restrict__ out) {
    __shared__ float sh[256];
    float s = 0.f;
    for (int i = threadIdx.x; i < 2048; i += 256) s += g_part[i];
    sh[threadIdx.x] = s;
    __syncthreads();
    for (int o = 128; o; o >>= 1) {
        if (threadIdx.x < o) sh[threadIdx.x] += sh[threadIdx.x + o];
        __syncthreads();
    }
    if (threadIdx.x == 0) out[0] = sh[0] * (1.f / 16.f);
}

// ---------------------------------------------------------------------------
extern "C" void kernel_launch(void* const* d_in, const int* in_sizes, int n_in,
                              void* d_out, int out_size) {
    const float* x = (const float*)d_in[0];
    const float* y = (const float*)d_in[1];
    float* out = (float*)d_out;

    sumsq_kernel<<<4096, 256>>>(x, y);
    cost_kernel<<<dim3(8, 8, 16), 256>>>(x, y);
    for (int it = 0; it < 50; ++it) {
        row_lse<<<2048, 256>>>();
        col_lse<<<dim3(8, 16), 128>>>();
    }
    transport_kernel<<<2048, 256>>>();
    finalize_kernel<<<1, 256>>>(out);
}

// round 3
// speedup vs baseline: 1.0378x; 1.0378x over previous
#include <cuda_runtime.h>
#include <math.h>

// Sinkhorn distance: B=16, Lx=Ly=1024, D=256, eps=0.1, 50 iters.
// All log-domain quantities are kept in log2 units:
//   lk2 = -cost * (10/ln2),  log_mu2 = log_nu2 = -log2(1024) = -10
// LSE2(x) = log2 sum 2^x  — identical recursion to the reference divided by ln2.

#define BATCH 16
#define LSEQ  1024
#define DDIM  256
#define K2C   14.426950408889634f   // 10 / ln(2)

__device__ float g_cost[(size_t)BATCH * LSEQ * LSEQ];  // 64 MB scratch
__device__ float g_x2[BATCH * LSEQ];
__device__ float g_y2[BATCH * LSEQ];
__device__ float g_lu[BATCH * LSEQ];
__device__ float g_lv[BATCH * LSEQ];
__device__ float g_part[2048];

static __device__ __forceinline__ float ex2f(float x) {
    float r; asm("ex2.approx.ftz.f32 %0, %1;" : "=f"(r) : "f"(x)); return r;
}
static __device__ __forceinline__ float lg2f(float x) {
    float r; asm("lg2.approx.ftz.f32 %0, %1;" : "=f"(r) : "f"(x)); return r;
}

typedef unsigned long long ull;
static __device__ __forceinline__ ull pack2(float lo, float hi) {
    ull r; asm("mov.b64 %0, {%1, %2};" : "=l"(r) : "f"(lo), "f"(hi)); return r;
}
static __device__ __forceinline__ float2 unpack2(ull v) {
    float2 r; asm("mov.b64 {%0, %1}, %2;" : "=f"(r.x), "=f"(r.y) : "l"(v)); return r;
}
static __device__ __forceinline__ void ffma2(ull& d, ull a, ull b) {
    asm("fma.rn.f32x2 %0, %1, %2, %0;" : "+l"(d) : "l"(a), "l"(b));
}

// ---------------------------------------------------------------------------
// Kernel 1: row sums of squares for x and y; also zero-init log_u / log_v.
// One warp per row (32768 rows total). grid 4096 x 256 threads.
// ---------------------------------------------------------------------------
__global__ __launch_bounds__(256) void sumsq_kernel(const float* __restrict__ x,
                                                    const float* __restrict__ y) {
    int warp = (blockIdx.x * 256 + threadIdx.x) >> 5;
    int lane = threadIdx.x & 31;
    int isx = (warp < BATCH * LSEQ);
    int r = isx ? warp : warp - BATCH * LSEQ;
    const float* src = isx ? x : y;
    const float4* p = (const float4*)(src + (size_t)r * DDIM);
    float s = 0.f;
#pragma unroll
    for (int t = 0; t < 2; t++) {
        float4 v = p[lane + 32 * t];
        s += v.x * v.x + v.y * v.y + v.z * v.z + v.w * v.w;
    }
#pragma unroll
    for (int o = 16; o; o >>= 1) s += __shfl_xor_sync(0xffffffffu, s, o);
    if (lane == 0) {
        if (isx) { g_x2[r] = s; g_lu[r] = 0.f; }
        else     { g_y2[r] = s; g_lv[r] = 0.f; }
    }
}

// ---------------------------------------------------------------------------
// Kernel 2: batched cost GEMM.  cost = sqrt(max(x2 + y2 - 2*x@y^T, 0)).
// 128x128 tile, BK=8, 256 threads, 8x8 microtile, packed f32x2 FMAs.
// grid (8 coltiles, 8 rowtiles, 16 batches).
// ---------------------------------------------------------------------------
__global__ __launch_bounds__(256, 2) void cost_kernel(const float* __restrict__ x,
                                                      const float* __restrict__ y) {
    __shared__ __align__(16) float As[8][128];
    __shared__ __align__(16) float Bs[8][128];
    int b = blockIdx.z;
    int i0 = blockIdx.y * 128;
    int j0 = blockIdx.x * 128;
    int tid = threadIdx.x;
    int tx = tid & 15, ty = tid >> 4;
    const float* xb = x + (size_t)b * LSEQ * DDIM;
    const float* yb = y + (size_t)b * LSEQ * DDIM;
    int lr = tid >> 1;            // load row 0..127
    int lc = (tid & 1) * 4;       // load col group 0 or 4

    ull acc[8][4];
#pragma unroll
    for (int ri = 0; ri < 8; ri++)
#pragma unroll
        for (int cj = 0; cj < 4; cj++) acc[ri][cj] = 0ull;

    for (int k0 = 0; k0 < DDIM; k0 += 8) {
        float4 av = *(const float4*)(xb + (size_t)(i0 + lr) * DDIM + k0 + lc);
        float4 bv = *(const float4*)(yb + (size_t)(j0 + lr) * DDIM + k0 + lc);
        __syncthreads();
        As[lc + 0][lr] = av.x; As[lc + 1][lr] = av.y;
        As[lc + 2][lr] = av.z; As[lc + 3][lr] = av.w;
        Bs[lc + 0][lr] = bv.x; Bs[lc + 1][lr] = bv.y;
        Bs[lc + 2][lr] = bv.z; Bs[lc + 3][lr] = bv.w;
        __syncthreads();
#pragma unroll
        for (int kk = 0; kk < 8; kk++) {
            float4 a0 = *(const float4*)&As[kk][ty * 8];
            float4 a1 = *(const float4*)&As[kk][ty * 8 + 4];
            float4 b0 = *(const float4*)&Bs[kk][tx * 8];
            float4 b1 = *(const float4*)&Bs[kk][tx * 8 + 4];
            ull bp[4];
            bp[0] = pack2(b0.x, b0.y); bp[1] = pack2(b0.z, b0.w);
            bp[2] = pack2(b1.x, b1.y); bp[3] = pack2(b1.z, b1.w);
            float a[8] = {a0.x, a0.y, a0.z, a0.w, a1.x, a1.y, a1.z, a1.w};
#pragma unroll
            for (int ri = 0; ri < 8; ri++) {
                ull ap = pack2(a[ri], a[ri]);
#pragma unroll
                for (int cj = 0; cj < 4; cj++) ffma2(acc[ri][cj], ap, bp[cj]);
            }
        }
    }

    float x2r[8], y2c[8];
#pragma unroll
    for (int ri = 0; ri < 8; ri++) x2r[ri] = g_x2[b * LSEQ + i0 + ty * 8 + ri];
#pragma unroll
    for (int c = 0; c < 8; c++)    y2c[c]  = g_y2[b * LSEQ + j0 + tx * 8 + c];

#pragma unroll
    for (int ri = 0; ri < 8; ri++) {
        float out[8];
#pragma unroll
        for (int cj = 0; cj < 4; cj++) {
            float2 u = unpack2(acc[ri][cj]);
            out[2 * cj] = u.x; out[2 * cj + 1] = u.y;
        }
#pragma unroll
        for (int c = 0; c < 8; c++) {
            float d2 = x2r[ri] + y2c[c] - 2.f * out[c];
            out[c] = sqrtf(fmaxf(d2, 0.f));
        }
        float* dst = g_cost + ((size_t)b << 20) + (size_t)(i0 + ty * 8 + ri) * LSEQ + j0 + tx * 8;
        *(float4*)dst       = make_float4(out[0], out[1], out[2], out[3]);
        *(float4*)(dst + 4) = make_float4(out[4], out[5], out[6], out[7]);
    }
}

// ---------------------------------------------------------------------------
// Kernel 3: row LSE update.  log_u = -10 - LSE2_j(lv[j] - K2*c[i,j]).
// One warp per row; entire 1024-elem row held in registers (exact max, 1 exp/elem).
// grid 2048 x 256 (8 warps/block).
// ---------------------------------------------------------------------------
__global__ __launch_bounds__(256) void row_lse(void) {
    int row = blockIdx.x * 8 + (threadIdx.x >> 5);
    int lane = threadIdx.x & 31;
    int b = row >> 10;
    const float4* c4 = (const float4*)(g_cost + ((size_t)row << 10));
    const float4* v4 = (const float4*)(g_lv + (b << 10));
    float a[32];
#pragma unroll
    for (int t = 0; t < 8; t++) {
        float4 c = c4[lane + 32 * t];
        float4 v = v4[lane + 32 * t];
        a[4 * t + 0] = fmaf(c.x, -K2C, v.x);
        a[4 * t + 1] = fmaf(c.y, -K2C, v.y);
        a[4 * t + 2] = fmaf(c.z, -K2C, v.z);
        a[4 * t + 3] = fmaf(c.w, -K2C, v.w);
    }
    float m = a[0];
#pragma unroll
    for (int e = 1; e < 32; e++) m = fmaxf(m, a[e]);
#pragma unroll
    for (int o = 16; o; o >>= 1) m = fmaxf(m, __shfl_xor_sync(0xffffffffu, m, o));
    float s = 0.f;
#pragma unroll
    for (int e = 0; e < 32; e++) s += ex2f(a[e] - m);
#pragma unroll
    for (int o = 16; o; o >>= 1) s += __shfl_xor_sync(0xffffffffu, s, o);
    if (lane == 0) g_lu[row] = -10.f - (m + lg2f(s));
}

// ---------------------------------------------------------------------------
// Kernel 4: column LSE update.  log_v = -10 - LSE2_i(lu[i] - K2*c[i,j]).
// Block = 32 columns x 1024 rows, split into 8 warp row-groups of 128 rows;
// partial (max, scaled-sum) merged in shared memory.
// grid (32 coltiles, 16 batches) x 256 threads = 512 blocks.
// ---------------------------------------------------------------------------
__global__ __launch_bounds__(256) void col_lse(void) {
    __shared__ float slu[1024];
    __shared__ float smx[256];
    __shared__ float ssm[256];
    int b = blockIdx.y;
    int tc = threadIdx.x & 31;        // column within 32-wide tile
    int rg = threadIdx.x >> 5;        // row group 0..7 (128 rows each)
    int col = blockIdx.x * 32 + tc;
#pragma unroll
    for (int k = threadIdx.x; k < 1024; k += 256) slu[k] = g_lu[(b << 10) + k];
    __syncthreads();
    const float* base = g_cost + ((size_t)b << 20) + ((size_t)(rg * 128) << 10) + col;
    float m = -1e30f, s = 0.f;
#pragma unroll 2
    for (int ch = 0; ch < 8; ch++) {
        float a[16];
#pragma unroll
        for (int r = 0; r < 16; r++) {
            float c = __ldg(base + ((size_t)(ch * 16 + r) << 10));
            a[r] = fmaf(c, -K2C, slu[rg * 128 + ch * 16 + r]);
        }
        float cm = a[0];
#pragma unroll
        for (int r = 1; r < 16; r++) cm = fmaxf(cm, a[r]);
        float M = fmaxf(m, cm);
        s *= ex2f(m - M);
#pragma unroll
        for (int r = 0; r < 16; r++) s += ex2f(a[r] - M);
        m = M;
    }
    smx[threadIdx.x] = m;
    ssm[threadIdx.x] = s;
    __syncthreads();
    if (threadIdx.x < 32) {
        float M = smx[threadIdx.x];
        float S = ssm[threadIdx.x];
#pragma unroll
        for (int g = 1; g < 8; g++) {
            float m2 = smx[g * 32 + threadIdx.x];
            float s2 = ssm[g * 32 + threadIdx.x];
            float Mn = fmaxf(M, m2);
            S = S * ex2f(M - Mn) + s2 * ex2f(m2 - Mn);
            M = Mn;
        }
        g_lv[(b << 10) + col] = -10.f - (M + lg2f(S));
    }
}

// ---------------------------------------------------------------------------
// Kernel 5: transport sum.  sum_ij 2^(lu_i + lv_j - K2*c) * c  (per block partial).
// Warp per row; deterministic block partials (no atomics).
// ---------------------------------------------------------------------------
__global__ __launch_bounds__(256) void transport_kernel(void) {
    __shared__ float wsum[8];
    int w = threadIdx.x >> 5;
    int row = blockIdx.x * 8 + w;
    int lane = threadIdx.x & 31;
    int b = row >> 10;
    float luI = g_lu[row];
    const float4* c4 = (const float4*)(g_cost + ((size_t)row << 10));
    const float4* v4 = (const float4*)(g_lv + (b << 10));
    float s = 0.f;
#pragma unroll
    for (int t = 0; t < 8; t++) {
        float4 c = c4[lane + 32 * t];
        float4 v = v4[lane + 32 * t];
        s += ex2f(fmaf(c.x, -K2C, luI + v.x)) * c.x;
        s += ex2f(fmaf(c.y, -K2C, luI + v.y)) * c.y;
        s += ex2f(fmaf(c.z, -K2C, luI + v.z)) * c.z;
        s += ex2f(fmaf(c.w, -K2C, luI + v.w)) * c.w;
    }
#pragma unroll
    for (int o = 16; o; o >>= 1) s += __shfl_xor_sync(0xffffffffu, s, o);
    if (lane == 0) wsum[w] = s;
    __syncthreads();
    if (threadIdx.x == 0) {
        float t = 0.f;
#pragma unroll
        for (int i = 0; i < 8; i++) t += wsum[i];
        g_part[blockIdx.x] = t;
    }
}

__global__ __launch_bounds__(256) void finalize_kernel(float* __restrict__ out) {
    __shared__ float sh[256];
    float s = 0.f;
    for (int i = threadIdx.x; i < 2048; i += 256) s += g_part[i];
    sh[threadIdx.x] = s;
    __syncthreads();
    for (int o = 128; o; o >>= 1) {
        if (threadIdx.x < o) sh[threadIdx.x] += sh[threadIdx.x + o];
        __syncthreads();
    }
    if (threadIdx.x == 0) out[0] = sh[0] * (1.f / 16.f);
}

// ---------------------------------------------------------------------------
extern "C" void kernel_launch(void* const* d_in, const int* in_sizes, int n_in,
                              void* d_out, int out_size) {
    const float* x = (const float*)d_in[0];
    const float* y = (const float*)d_in[1];
    float* out = (float*)d_out;

    sumsq_kernel<<<4096, 256>>>(x, y);
    cost_kernel<<<dim3(8, 8, 16), 256>>>(x, y);
    for (int it = 0; it < 50; ++it) {
        row_lse<<<2048, 256>>>();
        col_lse<<<dim3(32, 16), 256>>>();
    }
    transport_kernel<<<2048, 256>>>();
    finalize_kernel<<<1, 256>>>(out);
}

// round 4
// speedup vs baseline: 1.3385x; 1.2898x over previous
#include <cuda_runtime.h>
#include <math.h>

// Sinkhorn distance: B=16, Lx=Ly=1024, D=256, eps=0.1, 50 iters.
// Log-domain quantities kept in log2 units:
//   lk2 = -cost * (10/ln2),  log_mu2 = log_nu2 = -10
// All 50 iterations + transport + final reduce run in ONE persistent kernel
// (512 co-resident blocks, software grid barrier).

#define BATCH 16
#define LSEQ  1024
#define DDIM  256
#define K2C   14.426950408889634f   // 10 / ln(2)
#define NBLK  512
#define NTHR  256

__device__ float g_cost[(size_t)BATCH * LSEQ * LSEQ];  // 64 MB scratch
__device__ float g_x2[BATCH * LSEQ];
__device__ float g_y2[BATCH * LSEQ];
__device__ float g_lu[BATCH * LSEQ];
__device__ float g_lv[BATCH * LSEQ];
__device__ float g_part[NBLK];
__device__ unsigned g_bar_cnt = 0;
__device__ unsigned g_bar_gen = 0;

static __device__ __forceinline__ float ex2f(float x) {
    float r; asm("ex2.approx.ftz.f32 %0, %1;" : "=f"(r) : "f"(x)); return r;
}
static __device__ __forceinline__ float lg2f(float x) {
    float r; asm("lg2.approx.ftz.f32 %0, %1;" : "=f"(r) : "f"(x)); return r;
}

typedef unsigned long long ull;
static __device__ __forceinline__ ull pack2(float lo, float hi) {
    ull r; asm("mov.b64 %0, {%1, %2};" : "=l"(r) : "f"(lo), "f"(hi)); return r;
}
static __device__ __forceinline__ float2 unpack2(ull v) {
    float2 r; asm("mov.b64 {%0, %1}, %2;" : "=f"(r.x), "=f"(r.y) : "l"(v)); return r;
}
static __device__ __forceinline__ void ffma2(ull& d, ull a, ull b) {
    asm("fma.rn.f32x2 %0, %1, %2, %0;" : "+l"(d) : "l"(a), "l"(b));
}

// Sense-reversing grid barrier. Safe: 512 blocks, launch_bounds(256,4) caps
// regs at 64 -> 4 CTAs/SM * 148 = 592 co-resident >= 512, no deadlock.
static __device__ __forceinline__ void grid_barrier() {
    __syncthreads();
    if (threadIdx.x == 0) {
        __threadfence();
        unsigned gen = *(volatile unsigned*)&g_bar_gen;
        unsigned prev = atomicAdd(&g_bar_cnt, 1u);
        if (prev == NBLK - 1) {
            g_bar_cnt = 0;
            __threadfence();
            *(volatile unsigned*)&g_bar_gen = gen + 1;
        } else {
            while (*(volatile unsigned*)&g_bar_gen == gen) { __nanosleep(32); }
        }
        __threadfence();
    }
    __syncthreads();
}

// ---------------------------------------------------------------------------
// Kernel 1: row sums of squares for x and y; also zero-init log_u / log_v.
// ---------------------------------------------------------------------------
__global__ __launch_bounds__(256) void sumsq_kernel(const float* __restrict__ x,
                                                    const float* __restrict__ y) {
    int warp = (blockIdx.x * 256 + threadIdx.x) >> 5;
    int lane = threadIdx.x & 31;
    int isx = (warp < BATCH * LSEQ);
    int r = isx ? warp : warp - BATCH * LSEQ;
    const float* src = isx ? x : y;
    const float4* p = (const float4*)(src + (size_t)r * DDIM);
    float s = 0.f;
#pragma unroll
    for (int t = 0; t < 2; t++) {
        float4 v = p[lane + 32 * t];
        s += v.x * v.x + v.y * v.y + v.z * v.z + v.w * v.w;
    }
#pragma unroll
    for (int o = 16; o; o >>= 1) s += __shfl_xor_sync(0xffffffffu, s, o);
    if (lane == 0) {
        if (isx) { g_x2[r] = s; g_lu[r] = 0.f; }
        else     { g_y2[r] = s; g_lv[r] = 0.f; }
    }
}

// ---------------------------------------------------------------------------
// Kernel 2: batched cost GEMM.  cost = sqrt(max(x2 + y2 - 2*x@y^T, 0)).
// 128x128 tile, BK=8, 256 threads, 8x8 microtile, packed f32x2 FMAs.
// ---------------------------------------------------------------------------
__global__ __launch_bounds__(256, 2) void cost_kernel(const float* __restrict__ x,
                                                      const float* __restrict__ y) {
    __shared__ __align__(16) float As[8][128];
    __shared__ __align__(16) float Bs[8][128];
    int b = blockIdx.z;
    int i0 = blockIdx.y * 128;
    int j0 = blockIdx.x * 128;
    int tid = threadIdx.x;
    int tx = tid & 15, ty = tid >> 4;
    const float* xb = x + (size_t)b * LSEQ * DDIM;
    const float* yb = y + (size_t)b * LSEQ * DDIM;
    int lr = tid >> 1;
    int lc = (tid & 1) * 4;

    ull acc[8][4];
#pragma unroll
    for (int ri = 0; ri < 8; ri++)
#pragma unroll
        for (int cj = 0; cj < 4; cj++) acc[ri][cj] = 0ull;

    for (int k0 = 0; k0 < DDIM; k0 += 8) {
        float4 av = *(const float4*)(xb + (size_t)(i0 + lr) * DDIM + k0 + lc);
        float4 bv = *(const float4*)(yb + (size_t)(j0 + lr) * DDIM + k0 + lc);
        __syncthreads();
        As[lc + 0][lr] = av.x; As[lc + 1][lr] = av.y;
        As[lc + 2][lr] = av.z; As[lc + 3][lr] = av.w;
        Bs[lc + 0][lr] = bv.x; Bs[lc + 1][lr] = bv.y;
        Bs[lc + 2][lr] = bv.z; Bs[lc + 3][lr] = bv.w;
        __syncthreads();
#pragma unroll
        for (int kk = 0; kk < 8; kk++) {
            float4 a0 = *(const float4*)&As[kk][ty * 8];
            float4 a1 = *(const float4*)&As[kk][ty * 8 + 4];
            float4 b0 = *(const float4*)&Bs[kk][tx * 8];
            float4 b1 = *(const float4*)&Bs[kk][tx * 8 + 4];
            ull bp[4];
            bp[0] = pack2(b0.x, b0.y); bp[1] = pack2(b0.z, b0.w);
            bp[2] = pack2(b1.x, b1.y); bp[3] = pack2(b1.z, b1.w);
            float a[8] = {a0.x, a0.y, a0.z, a0.w, a1.x, a1.y, a1.z, a1.w};
#pragma unroll
            for (int ri = 0; ri < 8; ri++) {
                ull ap = pack2(a[ri], a[ri]);
#pragma unroll
                for (int cj = 0; cj < 4; cj++) ffma2(acc[ri][cj], ap, bp[cj]);
            }
        }
    }

    float x2r[8], y2c[8];
#pragma unroll
    for (int ri = 0; ri < 8; ri++) x2r[ri] = g_x2[b * LSEQ + i0 + ty * 8 + ri];
#pragma unroll
    for (int c = 0; c < 8; c++)    y2c[c]  = g_y2[b * LSEQ + j0 + tx * 8 + c];

#pragma unroll
    for (int ri = 0; ri < 8; ri++) {
        float out[8];
#pragma unroll
        for (int cj = 0; cj < 4; cj++) {
            float2 u = unpack2(acc[ri][cj]);
            out[2 * cj] = u.x; out[2 * cj + 1] = u.y;
        }
#pragma unroll
        for (int c = 0; c < 8; c++) {
            float d2 = x2r[ri] + y2c[c] - 2.f * out[c];
            out[c] = sqrtf(fmaxf(d2, 0.f));
        }
        float* dst = g_cost + ((size_t)b << 20) + (size_t)(i0 + ty * 8 + ri) * LSEQ + j0 + tx * 8;
        *(float4*)dst       = make_float4(out[0], out[1], out[2], out[3]);
        *(float4*)(dst + 4) = make_float4(out[4], out[5], out[6], out[7]);
    }
}

// ---------------------------------------------------------------------------
// Kernel 3: persistent Sinkhorn. 512 blocks x 256 threads, ALL 50 iterations,
// then transport sum + final reduction. lu/lv cross-barrier traffic via L2
// (__ldcg); cost matrix via default (L1-cached, read-only) path.
// ---------------------------------------------------------------------------
__global__ __launch_bounds__(NTHR, 4) void sinkhorn_persist(float* __restrict__ out) {
    __shared__ float slu[1024];
    __shared__ float smx[256];
    __shared__ float ssm[256];
    __shared__ float wsum[8];

    int tid = threadIdx.x;
    int w = tid >> 5;
    int lane = tid & 31;
    int wg = blockIdx.x * 8 + w;          // 0..4095: warp-per-row group

    for (int it = 0; it < 50; ++it) {
        // ---- row pass: log_u = -10 - LSE2_j(lv[j] - K2*c[r,j]); 4 rows/warp
#pragma unroll 1
        for (int k = 0; k < 4; ++k) {
            int row = wg + 4096 * k;
            int b = row >> 10;
            const float4* c4 = (const float4*)(g_cost + ((size_t)row << 10));
            const float4* v4 = (const float4*)(g_lv + (b << 10));
            float m = -1e30f, s = 0.f;
#pragma unroll
            for (int half = 0; half < 2; ++half) {
                float a[16];
#pragma unroll
                for (int t = 0; t < 4; ++t) {
                    float4 c = c4[lane + 32 * (half * 4 + t)];
                    float4 v = __ldcg(&v4[lane + 32 * (half * 4 + t)]);
                    a[4 * t + 0] = fmaf(c.x, -K2C, v.x);
                    a[4 * t + 1] = fmaf(c.y, -K2C, v.y);
                    a[4 * t + 2] = fmaf(c.z, -K2C, v.z);
                    a[4 * t + 3] = fmaf(c.w, -K2C, v.w);
                }
                float cm = a[0];
#pragma unroll
                for (int e = 1; e < 16; e++) cm = fmaxf(cm, a[e]);
                float M = fmaxf(m, cm);
                s *= ex2f(m - M);
#pragma unroll
                for (int e = 0; e < 16; e++) s += ex2f(a[e] - M);
                m = M;
            }
#pragma unroll
            for (int o = 16; o; o >>= 1) {
                float m2 = __shfl_xor_sync(0xffffffffu, m, o);
                float s2 = __shfl_xor_sync(0xffffffffu, s, o);
                float M = fmaxf(m, m2);
                s = s * ex2f(m - M) + s2 * ex2f(m2 - M);
                m = M;
            }
            if (lane == 0) g_lu[row] = -10.f - (m + lg2f(s));
        }
        grid_barrier();

        // ---- col pass: one 32-col x 1024-row tile per block
        {
            int b = blockIdx.x >> 5;
            int col = (blockIdx.x & 31) * 32 + (tid & 31);
            int rg = tid >> 5;            // row group 0..7 (128 rows each)
#pragma unroll
            for (int kk = tid; kk < 1024; kk += 256) slu[kk] = __ldcg(&g_lu[(b << 10) + kk]);
            __syncthreads();
            const float* base = g_cost + ((size_t)b << 20) + ((size_t)(rg * 128) << 10) + col;
            float m = -1e30f, s = 0.f;
#pragma unroll 2
            for (int ch = 0; ch < 8; ch++) {
                float a[16];
#pragma unroll
                for (int r = 0; r < 16; r++) {
                    float c = __ldg(base + ((size_t)(ch * 16 + r) << 10));
                    a[r] = fmaf(c, -K2C, slu[rg * 128 + ch * 16 + r]);
                }
                float cm = a[0];
#pragma unroll
                for (int r = 1; r < 16; r++) cm = fmaxf(cm, a[r]);
                float M = fmaxf(m, cm);
                s *= ex2f(m - M);
#pragma unroll
                for (int r = 0; r < 16; r++) s += ex2f(a[r] - M);
                m = M;
            }
            smx[tid] = m;
            ssm[tid] = s;
            __syncthreads();
            if (tid < 32) {
                float M = smx[tid];
                float S = ssm[tid];
#pragma unroll
                for (int g = 1; g < 8; g++) {
                    float m2 = smx[g * 32 + tid];
                    float s2 = ssm[g * 32 + tid];
                    float Mn = fmaxf(M, m2);
                    S = S * ex2f(M - Mn) + s2 * ex2f(m2 - Mn);
                    M = Mn;
                }
                g_lv[(b << 10) + col] = -10.f - (M + lg2f(S));
            }
            __syncthreads();
        }
        grid_barrier();
    }

    // ---- transport sum: same 4-rows-per-warp partition, block partials
    {
        float s = 0.f;
#pragma unroll 1
        for (int k = 0; k < 4; ++k) {
            int row = wg + 4096 * k;
            int b = row >> 10;
            float luI = __ldcg(&g_lu[row]);
            const float4* c4 = (const float4*)(g_cost + ((size_t)row << 10));
            const float4* v4 = (const float4*)(g_lv + (b << 10));
#pragma unroll
            for (int t = 0; t < 8; t++) {
                float4 c = c4[lane + 32 * t];
                float4 v = __ldcg(&v4[lane + 32 * t]);
                s += ex2f(fmaf(c.x, -K2C, luI + v.x)) * c.x;
                s += ex2f(fmaf(c.y, -K2C, luI + v.y)) * c.y;
                s += ex2f(fmaf(c.z, -K2C, luI + v.z)) * c.z;
                s += ex2f(fmaf(c.w, -K2C, luI + v.w)) * c.w;
            }
        }
#pragma unroll
        for (int o = 16; o; o >>= 1) s += __shfl_xor_sync(0xffffffffu, s, o);
        if (lane == 0) wsum[w] = s;
        __syncthreads();
        if (tid == 0) {
            float t = 0.f;
#pragma unroll
            for (int i = 0; i < 8; i++) t += wsum[i];
            g_part[blockIdx.x] = t;
        }
    }
    grid_barrier();

    // ---- final reduction on block 0
    if (blockIdx.x == 0) {
        float s = 0.f;
        for (int i = tid; i < NBLK; i += 256) s += __ldcg(&g_part[i]);
        smx[tid] = s;
        __syncthreads();
        for (int o = 128; o; o >>= 1) {
            if (tid < o) smx[tid] += smx[tid + o];
            __syncthreads();
        }
        if (tid == 0) out[0] = smx[0] * (1.f / 16.f);
    }
}

// ---------------------------------------------------------------------------
extern "C" void kernel_launch(void* const* d_in, const int* in_sizes, int n_in,
                              void* d_out, int out_size) {
    const float* x = (const float*)d_in[0];
    const float* y = (const float*)d_in[1];
    float* out = (float*)d_out;

    sumsq_kernel<<<4096, 256>>>(x, y);
    cost_kernel<<<dim3(8, 8, 16), 256>>>(x, y);
    sinkhorn_persist<<<NBLK, NTHR>>>(out);
}